// round 1
// baseline (speedup 1.0000x reference)
#include <cuda_runtime.h>

// Problem constants
#define BB 4
#define TT 2048
#define DD 1024
#define HH 16
#define HDIM 64
#define MROWS (BB * TT)            // 8192
#define QKV_N (3 * DD)             // 3072

// Scratch (allocation-free rule: __device__ globals)
__device__ float g_qkv[(size_t)MROWS * QKV_N];   // 96 MB: [8192][3072] = [Q|K|V] per row
__device__ float g_att[(size_t)MROWS * DD];      // 32 MB: [B,T,H*HD] attention output

// ---------------------------------------------------------------------------
// Generic fp32 GEMM + bias:  C[M,N] = A[M,K] @ B[K,N] + bias[N]
// 128x128 block tile, BK=16, 256 threads, 8x8 per-thread micro-tile.
// ---------------------------------------------------------------------------
__global__ __launch_bounds__(256) void gemm_bias_kernel(
    const float* __restrict__ A, const float* __restrict__ Bm,
    const float* __restrict__ bias, float* __restrict__ C,
    int M, int N, int K)
{
    constexpr int BM = 128, BN = 128, BK = 16, TM = 8, TN = 8;
    __shared__ float As[BK][BM];   // A tile stored transposed
    __shared__ float Bs[BK][BN];

    const int tid = threadIdx.x;
    const int bm = blockIdx.y * BM;
    const int bn = blockIdx.x * BN;
    const int tr = (tid >> 4) * TM;   // 0..120
    const int tc = (tid & 15) * TN;   // 0..120

    float acc[TM][TN];
#pragma unroll
    for (int i = 0; i < TM; i++)
#pragma unroll
        for (int j = 0; j < TN; j++) acc[i][j] = 0.0f;

    for (int k0 = 0; k0 < K; k0 += BK) {
        // Load A tile: 128 rows x 16 cols = 512 float4, 2 per thread
#pragma unroll
        for (int i = 0; i < 2; i++) {
            int idx = tid + i * 256;          // 0..511
            int r   = idx >> 2;               // 0..127
            int c4  = idx & 3;                // 0..3
            float4 a = *(const float4*)(A + (size_t)(bm + r) * K + k0 + c4 * 4);
            As[c4 * 4 + 0][r] = a.x;
            As[c4 * 4 + 1][r] = a.y;
            As[c4 * 4 + 2][r] = a.z;
            As[c4 * 4 + 3][r] = a.w;
        }
        // Load B tile: 16 rows x 128 cols = 512 float4, 2 per thread
#pragma unroll
        for (int i = 0; i < 2; i++) {
            int idx = tid + i * 256;
            int r   = idx >> 5;               // 0..15
            int c4  = idx & 31;               // 0..31
            *(float4*)(&Bs[r][c4 * 4]) =
                *(const float4*)(Bm + (size_t)(k0 + r) * N + bn + c4 * 4);
        }
        __syncthreads();

#pragma unroll
        for (int k = 0; k < BK; k++) {
            float ra[TM], rb[TN];
            *(float4*)&ra[0] = *(const float4*)&As[k][tr];
            *(float4*)&ra[4] = *(const float4*)&As[k][tr + 4];
            *(float4*)&rb[0] = *(const float4*)&Bs[k][tc];
            *(float4*)&rb[4] = *(const float4*)&Bs[k][tc + 4];
#pragma unroll
            for (int i = 0; i < TM; i++)
#pragma unroll
                for (int j = 0; j < TN; j++)
                    acc[i][j] += ra[i] * rb[j];
        }
        __syncthreads();
    }

#pragma unroll
    for (int i = 0; i < TM; i++) {
        float* crow = C + (size_t)(bm + tr + i) * N + bn + tc;
#pragma unroll
        for (int j = 0; j < TN; j += 4) {
            float4 o;
            o.x = acc[i][j + 0] + bias[bn + tc + j + 0];
            o.y = acc[i][j + 1] + bias[bn + tc + j + 1];
            o.z = acc[i][j + 2] + bias[bn + tc + j + 2];
            o.w = acc[i][j + 3] + bias[bn + tc + j + 3];
            *(float4*)(crow + j) = o;
        }
    }
}

// ---------------------------------------------------------------------------
// Causal flash attention, fp32. One block = 64 query rows of one (b,h).
// 64 threads; thread t owns query row (qt*64 + t): q and O in registers.
// K/V tiles (64x64) + P (key-major, [key][query]) in shared memory (48 KB).
// ---------------------------------------------------------------------------
__global__ __launch_bounds__(64) void attn_kernel(
    const float* __restrict__ qkv, float* __restrict__ out)
{
    constexpr int TS = 64;
    __shared__ float Ks[TS][HDIM];   // 16 KB
    __shared__ float Vs[TS][HDIM];   // 16 KB
    __shared__ float Ps[TS][TS];     // 16 KB  [key j][query tid] -> conflict-free

    const int tid = threadIdx.x;            // 0..63
    const int qt  = blockIdx.x;             // query tile
    const int h   = blockIdx.y;
    const int b   = blockIdx.z;
    const int q_glob = qt * TS + tid;

    const size_t rowstride = QKV_N;         // 3072 floats per token row

    // Load and pre-scale q (1/sqrt(64) = 0.125)
    const float* qrow = qkv + ((size_t)(b * TT + q_glob)) * rowstride + h * HDIM;
    float q[HDIM];
#pragma unroll
    for (int d = 0; d < HDIM; d++) q[d] = qrow[d] * 0.125f;

    float O[HDIM];
#pragma unroll
    for (int d = 0; d < HDIM; d++) O[d] = 0.0f;
    float m = -1e30f, l = 0.0f;

    for (int kt = 0; kt <= qt; kt++) {
        // Cooperative load of K and V tiles (vectorized, coalesced)
        const float* kbase = qkv + ((size_t)(b * TT + kt * TS)) * rowstride + DD + h * HDIM;
        const float* vbase = kbase + DD;
#pragma unroll
        for (int it = 0; it < 16; it++) {
            int idx = it * 64 + tid;        // 0..1023 float4 slots
            int row = idx >> 4;             // 0..63
            int c4  = idx & 15;             // 0..15
            *(float4*)&Ks[row][c4 * 4] = *(const float4*)(kbase + (size_t)row * rowstride + c4 * 4);
            *(float4*)&Vs[row][c4 * 4] = *(const float4*)(vbase + (size_t)row * rowstride + c4 * 4);
        }
        __syncthreads();

        const bool diag = (kt == qt);

        // S = q . K^T  (scores for this thread's query row)
        float mloc = -1e30f;
        for (int j = 0; j < TS; j++) {
            const float4* kr = (const float4*)Ks[j];
            float s = 0.0f;
#pragma unroll
            for (int d4 = 0; d4 < 16; d4++) {
                float4 kk = kr[d4];          // broadcast across warp
                s += q[d4 * 4 + 0] * kk.x + q[d4 * 4 + 1] * kk.y
                   + q[d4 * 4 + 2] * kk.z + q[d4 * 4 + 3] * kk.w;
            }
            if (diag && j > tid) s = -1e30f;     // causal mask
            Ps[j][tid] = s;                      // conflict-free store
            mloc = fmaxf(mloc, s);
        }

        // Online softmax update
        float mnew = fmaxf(m, mloc);
        float corr = __expf(m - mnew);           // 0 on first tile (m = -1e30)
        l *= corr;
#pragma unroll
        for (int d = 0; d < HDIM; d++) O[d] *= corr;

        float psum = 0.0f;
        for (int j = 0; j < TS; j++) {
            float p = __expf(Ps[j][tid] - mnew); // masked -> exp(-huge) = 0
            Ps[j][tid] = p;
            psum += p;
        }
        l += psum;
        m = mnew;

        // O += P @ V   (Ps conflict-free, Vs broadcast)
#pragma unroll
        for (int d4 = 0; d4 < 16; d4++) {
            float a0 = O[d4 * 4 + 0], a1 = O[d4 * 4 + 1];
            float a2 = O[d4 * 4 + 2], a3 = O[d4 * 4 + 3];
            for (int j = 0; j < TS; j++) {
                float  p = Ps[j][tid];
                float4 v = *(const float4*)&Vs[j][d4 * 4];
                a0 += p * v.x; a1 += p * v.y; a2 += p * v.z; a3 += p * v.w;
            }
            O[d4 * 4 + 0] = a0; O[d4 * 4 + 1] = a1;
            O[d4 * 4 + 2] = a2; O[d4 * 4 + 3] = a3;
        }
        __syncthreads();   // before next tile overwrites Ks/Vs
    }

    // Normalize and write out in [B, T, H*HD] layout
    const float inv = 1.0f / l;
    float* orow = out + ((size_t)(b * TT + q_glob)) * DD + h * HDIM;
#pragma unroll
    for (int d4 = 0; d4 < 16; d4++) {
        float4 o;
        o.x = O[d4 * 4 + 0] * inv;
        o.y = O[d4 * 4 + 1] * inv;
        o.z = O[d4 * 4 + 2] * inv;
        o.w = O[d4 * 4 + 3] * inv;
        *(float4*)(orow + d4 * 4) = o;
    }
}

// ---------------------------------------------------------------------------
// Launch: QKV GEMM -> causal attention -> proj GEMM
// ---------------------------------------------------------------------------
extern "C" void kernel_launch(void* const* d_in, const int* in_sizes, int n_in,
                              void* d_out, int out_size)
{
    const float* x      = (const float*)d_in[0];
    const float* qkv_w  = (const float*)d_in[1];
    const float* qkv_b  = (const float*)d_in[2];
    const float* proj_w = (const float*)d_in[3];
    const float* proj_b = (const float*)d_in[4];
    float* out = (float*)d_out;

    float *qkv_s, *att_s;
    cudaGetSymbolAddress((void**)&qkv_s, g_qkv);
    cudaGetSymbolAddress((void**)&att_s, g_att);

    // 1) QKV GEMM: [8192,1024] @ [1024,3072] + bias
    dim3 g1(QKV_N / 128, MROWS / 128);
    gemm_bias_kernel<<<g1, 256>>>(x, qkv_w, qkv_b, qkv_s, MROWS, QKV_N, DD);

    // 2) Causal multi-head attention
    dim3 ga(TT / 64, HH, BB);
    attn_kernel<<<ga, 64>>>(qkv_s, att_s);

    // 3) Output projection: [8192,1024] @ [1024,1024] + bias
    dim3 g2(DD / 128, MROWS / 128);
    gemm_bias_kernel<<<g2, 256>>>(att_s, proj_w, proj_b, out, MROWS, DD, DD);
}

// round 2
// speedup vs baseline: 1.5461x; 1.5461x over previous
#include <cuda_runtime.h>
#include <cstdint>

// Problem constants
#define BB 4
#define TT 2048
#define DD 1024
#define HH 16
#define HDIM 64
#define MROWS (BB * TT)            // 8192
#define QKV_N (3 * DD)             // 3072

// Scratch (allocation-free rule: __device__ globals)
__device__ float g_qkv[(size_t)MROWS * QKV_N];   // 96 MB
__device__ float g_att[(size_t)MROWS * DD];      // 32 MB

// ---------------------------------------------------------------------------
// TF32 tensor-core GEMM + bias: C[M,N] = A[M,K] @ B[K,N] + bias[N]
// 128x128x32 block tile, 256 threads (8 warps), warp = 64Mx32N,
// mma.sync.m16n8k8 tf32. A in SMEM pitch-36 (conflict-free frags),
// B in SMEM with XOR-8 swizzle (conflict-free frags + stores).
// ---------------------------------------------------------------------------
__device__ __forceinline__ uint32_t f2tf32(float x) {
    uint32_t u;
    asm("cvt.rna.tf32.f32 %0, %1;" : "=r"(u) : "f"(x));
    return u;
}

__global__ __launch_bounds__(256) void gemm_tf32_kernel(
    const float* __restrict__ A, const float* __restrict__ Bm,
    const float* __restrict__ bias, float* __restrict__ C,
    int M, int N, int K)
{
    constexpr int BM = 128, BN = 128, BK = 32;
    constexpr int AP = 36;                         // A smem pitch (words)
    __shared__ uint32_t As[BM * AP];               // 18432 B
    __shared__ uint32_t Bs[BK * BN];               // 16384 B

    const int tid  = threadIdx.x;
    const int lane = tid & 31;
    const int warp = tid >> 5;
    const int bm = blockIdx.y * BM;
    const int bn = blockIdx.x * BN;
    const int wm = (warp & 1) * 64;                // warp M offset
    const int wn = (warp >> 1) * 32;               // warp N offset
    const int gr = lane >> 2;                      // 0..7
    const int gc = lane & 3;                       // 0..3

    float c[4][4][4];                              // [mAtom][nAtom][4]
#pragma unroll
    for (int i = 0; i < 4; i++)
#pragma unroll
        for (int j = 0; j < 4; j++)
#pragma unroll
            for (int r = 0; r < 4; r++) c[i][j][r] = 0.0f;

    for (int k0 = 0; k0 < K; k0 += BK) {
        // ---- stage A tile (128x32), convert to tf32 ----
#pragma unroll
        for (int i = 0; i < 4; i++) {
            int idx = i * 256 + tid;               // 0..1023
            int r   = idx >> 3;                    // 0..127
            int c4  = (idx & 7) * 4;               // 0..28
            float4 v = *(const float4*)(A + (size_t)(bm + r) * K + k0 + c4);
            uint4 t;
            t.x = f2tf32(v.x); t.y = f2tf32(v.y);
            t.z = f2tf32(v.z); t.w = f2tf32(v.w);
            *(uint4*)&As[r * AP + c4] = t;
        }
        // ---- stage B tile (32x128), XOR swizzle ----
#pragma unroll
        for (int i = 0; i < 4; i++) {
            int idx = i * 256 + tid;
            int kr  = idx >> 5;                    // 0..31
            int c4  = (idx & 31) * 4;              // 0..124
            float4 v = *(const float4*)(Bm + (size_t)(k0 + kr) * N + bn + c4);
            uint4 t;
            t.x = f2tf32(v.x); t.y = f2tf32(v.y);
            t.z = f2tf32(v.z); t.w = f2tf32(v.w);
            int cs = c4 ^ ((kr & 3) * 8);
            *(uint4*)&Bs[kr * BN + cs] = t;
        }
        __syncthreads();

#pragma unroll
        for (int ks = 0; ks < 4; ks++) {
            const int kb = ks * 8;
            // A fragments: 4 m-atoms
            uint32_t a[4][4];
#pragma unroll
            for (int i = 0; i < 4; i++) {
                const uint32_t* ar = &As[(wm + i * 16 + gr) * AP + kb + gc];
                a[i][0] = ar[0];
                a[i][1] = ar[8 * AP];
                a[i][2] = ar[4];
                a[i][3] = ar[8 * AP + 4];
            }
            // B fragments: 4 n-atoms
            uint32_t b[4][2];
#pragma unroll
            for (int j = 0; j < 4; j++) {
                int n  = wn + j * 8 + gr;
                int k1 = kb + gc;
                int k2 = kb + gc + 4;
                b[j][0] = Bs[k1 * BN + (n ^ ((k1 & 3) * 8))];
                b[j][1] = Bs[k2 * BN + (n ^ ((k2 & 3) * 8))];
            }
#pragma unroll
            for (int i = 0; i < 4; i++)
#pragma unroll
                for (int j = 0; j < 4; j++) {
                    asm volatile(
                        "mma.sync.aligned.m16n8k8.row.col.f32.tf32.tf32.f32 "
                        "{%0,%1,%2,%3}, {%4,%5,%6,%7}, {%8,%9}, {%0,%1,%2,%3};"
                        : "+f"(c[i][j][0]), "+f"(c[i][j][1]),
                          "+f"(c[i][j][2]), "+f"(c[i][j][3])
                        : "r"(a[i][0]), "r"(a[i][1]), "r"(a[i][2]), "r"(a[i][3]),
                          "r"(b[j][0]), "r"(b[j][1]));
                }
        }
        __syncthreads();
    }

    // ---- epilogue: bias + store ----
#pragma unroll
    for (int i = 0; i < 4; i++) {
#pragma unroll
        for (int j = 0; j < 4; j++) {
            int row = bm + wm + i * 16 + gr;
            int col = bn + wn + j * 8 + 2 * gc;
            float bx = bias[col], by = bias[col + 1];
            float2 o0 = make_float2(c[i][j][0] + bx, c[i][j][1] + by);
            float2 o1 = make_float2(c[i][j][2] + bx, c[i][j][3] + by);
            *(float2*)(C + (size_t)row * N + col)       = o0;
            *(float2*)(C + (size_t)(row + 8) * N + col) = o1;
        }
    }
}

// ---------------------------------------------------------------------------
// Causal flash attention, fp32 SIMT (improved).
// Block = 128 query rows of one (b,h), 128 threads (1 query/thread).
// K/V tiles 64x64 in SMEM; scores in SMEM [key][query]; exp fused into PV.
// Dynamic SMEM: 64 KB.
// ---------------------------------------------------------------------------
__global__ __launch_bounds__(128, 2) void attn_kernel(
    const float* __restrict__ qkv, float* __restrict__ out)
{
    constexpr int TS = 64;     // key tile
    constexpr int QT = 128;    // queries per block
    extern __shared__ float sm[];
    float* Ks = sm;                        // [TS][HDIM] 16 KB
    float* Vs = sm + TS * HDIM;            // [TS][HDIM] 16 KB
    float* Ss = sm + 2 * TS * HDIM;        // [TS][QT]   32 KB

    const int tid = threadIdx.x;           // 0..127
    const int qt  = blockIdx.x;
    const int h   = blockIdx.y;
    const int b   = blockIdx.z;
    const int q_glob = qt * QT + tid;
    const size_t rs = QKV_N;               // 3072

    // Load and pre-scale q (1/sqrt(64) = 0.125)
    const float* qrow = qkv + ((size_t)(b * TT + q_glob)) * rs + h * HDIM;
    float q[HDIM];
#pragma unroll
    for (int d4 = 0; d4 < 16; d4++) {
        float4 v = *(const float4*)(qrow + d4 * 4);
        q[d4 * 4 + 0] = v.x * 0.125f; q[d4 * 4 + 1] = v.y * 0.125f;
        q[d4 * 4 + 2] = v.z * 0.125f; q[d4 * 4 + 3] = v.w * 0.125f;
    }

    float O[HDIM];
#pragma unroll
    for (int d = 0; d < HDIM; d++) O[d] = 0.0f;
    float m = -1e30f, l = 0.0f;

    const int ntiles = 2 * qt + 2;         // covers keys 0 .. qt*128+127
    for (int kt = 0; kt < ntiles; kt++) {
        // Cooperative K/V tile load: 64 rows x 16 float4 = 1024 slots
        const float* kbase = qkv + ((size_t)(b * TT + kt * TS)) * rs + DD + h * HDIM;
        const float* vbase = kbase + DD;
#pragma unroll
        for (int it = 0; it < 8; it++) {
            int idx = it * 128 + tid;
            int row = idx >> 4;
            int c4  = idx & 15;
            *(float4*)&Ks[row * HDIM + c4 * 4] =
                *(const float4*)(kbase + (size_t)row * rs + c4 * 4);
            *(float4*)&Vs[row * HDIM + c4 * 4] =
                *(const float4*)(vbase + (size_t)row * rs + c4 * 4);
        }
        __syncthreads();

        // S = q . K^T (+ causal mask), scores to SMEM
        float mloc = -1e30f;
        const int kbase_idx = kt * TS;
        for (int j = 0; j < TS; j++) {
            const float4* kr = (const float4*)&Ks[j * HDIM];
            float s0 = 0.f, s1 = 0.f, s2 = 0.f, s3 = 0.f;
#pragma unroll
            for (int d4 = 0; d4 < 16; d4 += 4) {
                float4 k0 = kr[d4], k1 = kr[d4 + 1], k2 = kr[d4 + 2], k3 = kr[d4 + 3];
                s0 += q[d4*4+0]*k0.x + q[d4*4+1]*k0.y + q[d4*4+2]*k0.z + q[d4*4+3]*k0.w;
                s1 += q[d4*4+4]*k1.x + q[d4*4+5]*k1.y + q[d4*4+6]*k1.z + q[d4*4+7]*k1.w;
                s2 += q[d4*4+8]*k2.x + q[d4*4+9]*k2.y + q[d4*4+10]*k2.z + q[d4*4+11]*k2.w;
                s3 += q[d4*4+12]*k3.x + q[d4*4+13]*k3.y + q[d4*4+14]*k3.z + q[d4*4+15]*k3.w;
            }
            float s = (s0 + s1) + (s2 + s3);
            if (kbase_idx + j > q_glob) s = -1e30f;
            Ss[j * QT + tid] = s;
            mloc = fmaxf(mloc, s);
        }

        // Online softmax rescale
        float mnew = fmaxf(m, mloc);
        float corr = __expf(m - mnew);
        l *= corr;
#pragma unroll
        for (int d = 0; d < HDIM; d++) O[d] *= corr;

        // Fused exp + PV accumulate
        float psum = 0.0f;
        for (int j = 0; j < TS; j++) {
            float p = __expf(Ss[j * QT + tid] - mnew);
            psum += p;
            const float4* vr = (const float4*)&Vs[j * HDIM];
#pragma unroll
            for (int d4 = 0; d4 < 16; d4++) {
                float4 v = vr[d4];
                O[d4*4+0] += p * v.x; O[d4*4+1] += p * v.y;
                O[d4*4+2] += p * v.z; O[d4*4+3] += p * v.w;
            }
        }
        l += psum;
        m = mnew;
        __syncthreads();
    }

    const float inv = 1.0f / l;
    float* orow = out + ((size_t)(b * TT + q_glob)) * DD + h * HDIM;
#pragma unroll
    for (int d4 = 0; d4 < 16; d4++) {
        float4 o;
        o.x = O[d4*4+0] * inv; o.y = O[d4*4+1] * inv;
        o.z = O[d4*4+2] * inv; o.w = O[d4*4+3] * inv;
        *(float4*)(orow + d4 * 4) = o;
    }
}

// ---------------------------------------------------------------------------
// Launch: QKV GEMM -> causal attention -> proj GEMM
// ---------------------------------------------------------------------------
extern "C" void kernel_launch(void* const* d_in, const int* in_sizes, int n_in,
                              void* d_out, int out_size)
{
    const float* x      = (const float*)d_in[0];
    const float* qkv_w  = (const float*)d_in[1];
    const float* qkv_b  = (const float*)d_in[2];
    const float* proj_w = (const float*)d_in[3];
    const float* proj_b = (const float*)d_in[4];
    float* out = (float*)d_out;

    float *qkv_s, *att_s;
    cudaGetSymbolAddress((void**)&qkv_s, g_qkv);
    cudaGetSymbolAddress((void**)&att_s, g_att);

    const int ATTN_SMEM = (64 * 64 * 2 + 64 * 128) * sizeof(float);  // 64 KB
    cudaFuncSetAttribute(attn_kernel,
                         cudaFuncAttributeMaxDynamicSharedMemorySize, ATTN_SMEM);

    // 1) QKV GEMM: [8192,1024] @ [1024,3072] + bias
    dim3 g1(QKV_N / 128, MROWS / 128);
    gemm_tf32_kernel<<<g1, 256>>>(x, qkv_w, qkv_b, qkv_s, MROWS, QKV_N, DD);

    // 2) Causal multi-head attention
    dim3 ga(TT / 128, HH, BB);
    attn_kernel<<<ga, 128, ATTN_SMEM>>>(qkv_s, att_s);

    // 3) Output projection: [8192,1024] @ [1024,1024] + bias
    dim3 g2(DD / 128, MROWS / 128);
    gemm_tf32_kernel<<<g2, 256>>>(att_s, proj_w, proj_b, out, MROWS, DD, DD);
}

// round 3
// speedup vs baseline: 3.8501x; 2.4902x over previous
#include <cuda_runtime.h>
#include <cstdint>

// Problem constants
#define BB 4
#define TT 2048
#define DD 1024
#define HH 16
#define HDIM 64
#define MROWS (BB * TT)            // 8192
#define QKV_N (3 * DD)             // 3072

// Scratch (allocation-free rule: __device__ globals)
__device__ float g_qkv[(size_t)MROWS * QKV_N];   // 96 MB
__device__ float g_att[(size_t)MROWS * DD];      // 32 MB

__device__ __forceinline__ uint32_t f2tf32(float x) {
    uint32_t u;
    asm("cvt.rna.tf32.f32 %0, %1;" : "=r"(u) : "f"(x));
    return u;
}

__device__ __forceinline__ void mma_tf32(float c[4], const uint32_t a[4],
                                         uint32_t b0, uint32_t b1) {
    asm volatile(
        "mma.sync.aligned.m16n8k8.row.col.f32.tf32.tf32.f32 "
        "{%0,%1,%2,%3}, {%4,%5,%6,%7}, {%8,%9}, {%0,%1,%2,%3};"
        : "+f"(c[0]), "+f"(c[1]), "+f"(c[2]), "+f"(c[3])
        : "r"(a[0]), "r"(a[1]), "r"(a[2]), "r"(a[3]), "r"(b0), "r"(b1));
}

// ---------------------------------------------------------------------------
// TF32 tensor-core GEMM + bias (unchanged from R2): C = A @ B + bias
// ---------------------------------------------------------------------------
__global__ __launch_bounds__(256) void gemm_tf32_kernel(
    const float* __restrict__ A, const float* __restrict__ Bm,
    const float* __restrict__ bias, float* __restrict__ C,
    int M, int N, int K)
{
    constexpr int BM = 128, BN = 128, BK = 32;
    constexpr int AP = 36;
    __shared__ uint32_t As[BM * AP];
    __shared__ uint32_t Bs[BK * BN];

    const int tid  = threadIdx.x;
    const int lane = tid & 31;
    const int warp = tid >> 5;
    const int bm = blockIdx.y * BM;
    const int bn = blockIdx.x * BN;
    const int wm = (warp & 1) * 64;
    const int wn = (warp >> 1) * 32;
    const int gr = lane >> 2;
    const int gc = lane & 3;

    float c[4][4][4];
#pragma unroll
    for (int i = 0; i < 4; i++)
#pragma unroll
        for (int j = 0; j < 4; j++)
#pragma unroll
            for (int r = 0; r < 4; r++) c[i][j][r] = 0.0f;

    for (int k0 = 0; k0 < K; k0 += BK) {
#pragma unroll
        for (int i = 0; i < 4; i++) {
            int idx = i * 256 + tid;
            int r   = idx >> 3;
            int c4  = (idx & 7) * 4;
            float4 v = *(const float4*)(A + (size_t)(bm + r) * K + k0 + c4);
            uint4 t;
            t.x = f2tf32(v.x); t.y = f2tf32(v.y);
            t.z = f2tf32(v.z); t.w = f2tf32(v.w);
            *(uint4*)&As[r * AP + c4] = t;
        }
#pragma unroll
        for (int i = 0; i < 4; i++) {
            int idx = i * 256 + tid;
            int kr  = idx >> 5;
            int c4  = (idx & 31) * 4;
            float4 v = *(const float4*)(Bm + (size_t)(k0 + kr) * N + bn + c4);
            uint4 t;
            t.x = f2tf32(v.x); t.y = f2tf32(v.y);
            t.z = f2tf32(v.z); t.w = f2tf32(v.w);
            int cs = c4 ^ ((kr & 3) * 8);
            *(uint4*)&Bs[kr * BN + cs] = t;
        }
        __syncthreads();

#pragma unroll
        for (int ks = 0; ks < 4; ks++) {
            const int kb = ks * 8;
            uint32_t a[4][4];
#pragma unroll
            for (int i = 0; i < 4; i++) {
                const uint32_t* ar = &As[(wm + i * 16 + gr) * AP + kb + gc];
                a[i][0] = ar[0];
                a[i][1] = ar[8 * AP];
                a[i][2] = ar[4];
                a[i][3] = ar[8 * AP + 4];
            }
            uint32_t b[4][2];
#pragma unroll
            for (int j = 0; j < 4; j++) {
                int n  = wn + j * 8 + gr;
                int k1 = kb + gc;
                int k2 = kb + gc + 4;
                b[j][0] = Bs[k1 * BN + (n ^ ((k1 & 3) * 8))];
                b[j][1] = Bs[k2 * BN + (n ^ ((k2 & 3) * 8))];
            }
#pragma unroll
            for (int i = 0; i < 4; i++)
#pragma unroll
                for (int j = 0; j < 4; j++)
                    mma_tf32(c[i][j], a[i], b[j][0], b[j][1]);
        }
        __syncthreads();
    }

#pragma unroll
    for (int i = 0; i < 4; i++) {
#pragma unroll
        for (int j = 0; j < 4; j++) {
            int row = bm + wm + i * 16 + gr;
            int col = bn + wn + j * 8 + 2 * gc;
            float bx = bias[col], by = bias[col + 1];
            float2 o0 = make_float2(c[i][j][0] + bx, c[i][j][1] + by);
            float2 o1 = make_float2(c[i][j][2] + bx, c[i][j][3] + by);
            *(float2*)(C + (size_t)row * N + col)       = o0;
            *(float2*)(C + (size_t)(row + 8) * N + col) = o1;
        }
    }
}

// ---------------------------------------------------------------------------
// Tensor-core causal flash attention (TF32 mma).
// Block: 64 queries of one (b,h); 128 threads, 4 warps (16 query rows/warp).
// Q fragments live in registers; P round-trips through the dead Q buffer.
// SMEM: QP[64][68] + K[64][68] + V[64][64] (xor swizzle) = 51200 B dynamic.
// ---------------------------------------------------------------------------
__global__ __launch_bounds__(128, 3) void attn_tc_kernel(
    const float* __restrict__ qkv, float* __restrict__ out)
{
    constexpr int QP = 68;                 // pitch (words) for QP / K tiles
    extern __shared__ uint32_t sm[];
    uint32_t* QPs = sm;                    // [64][68] Q staging, then P
    uint32_t* Ks  = sm + 64 * QP;          // [64][68]
    uint32_t* Vs  = sm + 2 * 64 * QP;      // [64][64] xor-swizzled

    const int tid  = threadIdx.x;
    const int lane = tid & 31;
    const int w    = tid >> 5;             // warp 0..3
    const int gr   = lane >> 2;            // 0..7
    const int gc   = lane & 3;             // 0..3
    const int qt = blockIdx.x;
    const int h  = blockIdx.y;
    const int b  = blockIdx.z;
    const size_t rs = QKV_N;

    // ---- stage Q tile (scaled by 1/8, tf32) ----
    const float* qbase = qkv + ((size_t)(b * TT + qt * 64)) * rs + h * HDIM;
#pragma unroll
    for (int it = 0; it < 8; it++) {
        int idx = it * 128 + tid;
        int row = idx >> 4;
        int c4  = (idx & 15) * 4;
        float4 v = *(const float4*)(qbase + (size_t)row * rs + c4);
        uint4 t;
        t.x = f2tf32(v.x * 0.125f); t.y = f2tf32(v.y * 0.125f);
        t.z = f2tf32(v.z * 0.125f); t.w = f2tf32(v.w * 0.125f);
        *(uint4*)&QPs[row * QP + c4] = t;
    }
    __syncthreads();

    // ---- Q fragments for this warp (rows w*16 .. w*16+15), all 8 k-chunks ----
    uint32_t qf[8][4];
    {
        const uint32_t* qb = &QPs[(w * 16 + gr) * QP + gc];
#pragma unroll
        for (int ks = 0; ks < 8; ks++) {
            qf[ks][0] = qb[ks * 8];
            qf[ks][1] = qb[8 * QP + ks * 8];
            qf[ks][2] = qb[ks * 8 + 4];
            qf[ks][3] = qb[8 * QP + ks * 8 + 4];
        }
    }

    float o[8][4];
#pragma unroll
    for (int j = 0; j < 8; j++)
#pragma unroll
        for (int r = 0; r < 4; r++) o[j][r] = 0.0f;
    float m0 = -1e30f, m1 = -1e30f, l0 = 0.0f, l1 = 0.0f;

    for (int kt = 0; kt <= qt; kt++) {
        // ---- stage K (pitch 68) and V (xor swizzle), tf32 ----
        const float* kbg = qkv + ((size_t)(b * TT + kt * 64)) * rs + DD + h * HDIM;
        const float* vbg = kbg + DD;
#pragma unroll
        for (int it = 0; it < 8; it++) {
            int idx = it * 128 + tid;
            int row = idx >> 4;
            int c4  = (idx & 15) * 4;
            float4 kv = *(const float4*)(kbg + (size_t)row * rs + c4);
            uint4 t;
            t.x = f2tf32(kv.x); t.y = f2tf32(kv.y);
            t.z = f2tf32(kv.z); t.w = f2tf32(kv.w);
            *(uint4*)&Ks[row * QP + c4] = t;
            float4 vv = *(const float4*)(vbg + (size_t)row * rs + c4);
            uint4 u;
            u.x = f2tf32(vv.x); u.y = f2tf32(vv.y);
            u.z = f2tf32(vv.z); u.w = f2tf32(vv.w);
            *(uint4*)&Vs[row * 64 + (c4 ^ ((row & 3) * 8))] = u;
        }
        __syncthreads();

        // ---- S = Q @ K^T ----
        float s[8][4];
#pragma unroll
        for (int j = 0; j < 8; j++) {
            s[j][0] = s[j][1] = s[j][2] = s[j][3] = 0.0f;
            const uint32_t* kb2 = &Ks[(j * 8 + gr) * QP + gc];
#pragma unroll
            for (int ks = 0; ks < 8; ks++)
                mma_tf32(s[j], qf[ks], kb2[ks * 8], kb2[ks * 8 + 4]);
        }

        // ---- causal mask (diagonal tile only; TS == QT == 64) ----
        if (kt == qt) {
            int row_l = w * 16 + gr;
#pragma unroll
            for (int j = 0; j < 8; j++) {
                int key_l = j * 8 + 2 * gc;
                if (key_l     > row_l)     s[j][0] = -1e30f;
                if (key_l + 1 > row_l)     s[j][1] = -1e30f;
                if (key_l     > row_l + 8) s[j][2] = -1e30f;
                if (key_l + 1 > row_l + 8) s[j][3] = -1e30f;
            }
        }

        // ---- online softmax (row state in registers, quad shfl reduce) ----
        float mx0 = -1e30f, mx1 = -1e30f;
#pragma unroll
        for (int j = 0; j < 8; j++) {
            mx0 = fmaxf(mx0, fmaxf(s[j][0], s[j][1]));
            mx1 = fmaxf(mx1, fmaxf(s[j][2], s[j][3]));
        }
        mx0 = fmaxf(mx0, __shfl_xor_sync(0xffffffffu, mx0, 1));
        mx0 = fmaxf(mx0, __shfl_xor_sync(0xffffffffu, mx0, 2));
        mx1 = fmaxf(mx1, __shfl_xor_sync(0xffffffffu, mx1, 1));
        mx1 = fmaxf(mx1, __shfl_xor_sync(0xffffffffu, mx1, 2));

        float mn0 = fmaxf(m0, mx0), mn1 = fmaxf(m1, mx1);
        float cr0 = __expf(m0 - mn0), cr1 = __expf(m1 - mn1);
        l0 *= cr0; l1 *= cr1;
#pragma unroll
        for (int j = 0; j < 8; j++) {
            o[j][0] *= cr0; o[j][1] *= cr0;
            o[j][2] *= cr1; o[j][3] *= cr1;
        }

        float rs0 = 0.0f, rs1 = 0.0f;
        uint32_t* prow = &QPs[(w * 16 + gr) * QP + 2 * gc];
#pragma unroll
        for (int j = 0; j < 8; j++) {
            float p0 = __expf(s[j][0] - mn0);
            float p1 = __expf(s[j][1] - mn0);
            float p2 = __expf(s[j][2] - mn1);
            float p3 = __expf(s[j][3] - mn1);
            rs0 += p0 + p1; rs1 += p2 + p3;
            *(uint2*)&prow[j * 8]          = make_uint2(f2tf32(p0), f2tf32(p1));
            *(uint2*)&prow[8 * QP + j * 8] = make_uint2(f2tf32(p2), f2tf32(p3));
        }
        rs0 += __shfl_xor_sync(0xffffffffu, rs0, 1);
        rs0 += __shfl_xor_sync(0xffffffffu, rs0, 2);
        rs1 += __shfl_xor_sync(0xffffffffu, rs1, 1);
        rs1 += __shfl_xor_sync(0xffffffffu, rs1, 2);
        l0 += rs0; l1 += rs1;
        m0 = mn0; m1 = mn1;
        __syncwarp();   // P rows are warp-private; warp-level visibility suffices

        // ---- P fragments ----
        uint32_t pf[8][4];
        {
            const uint32_t* pb = &QPs[(w * 16 + gr) * QP + gc];
#pragma unroll
            for (int kc = 0; kc < 8; kc++) {
                pf[kc][0] = pb[kc * 8];
                pf[kc][1] = pb[8 * QP + kc * 8];
                pf[kc][2] = pb[kc * 8 + 4];
                pf[kc][3] = pb[8 * QP + kc * 8 + 4];
            }
        }

        // ---- O += P @ V ----
#pragma unroll
        for (int j = 0; j < 8; j++) {
            const int csw = (j * 8 + gr) ^ (gc * 8);
#pragma unroll
            for (int kc = 0; kc < 8; kc++) {
                uint32_t b0 = Vs[(kc * 8 + gc) * 64 + csw];
                uint32_t b1 = Vs[(kc * 8 + gc + 4) * 64 + csw];
                mma_tf32(o[j], pf[kc], b0, b1);
            }
        }
        __syncthreads();   // all warps done with Ks/Vs before next tile load
    }

    // ---- epilogue: normalize, write [B,T,H*HD] ----
    float iv0 = 1.0f / l0, iv1 = 1.0f / l1;
    int q0 = qt * 64 + w * 16 + gr;
    float* out0 = out + ((size_t)(b * TT + q0)) * DD + h * HDIM + 2 * gc;
    float* out1 = out0 + (size_t)8 * DD;
#pragma unroll
    for (int j = 0; j < 8; j++) {
        *(float2*)(out0 + j * 8) = make_float2(o[j][0] * iv0, o[j][1] * iv0);
        *(float2*)(out1 + j * 8) = make_float2(o[j][2] * iv1, o[j][3] * iv1);
    }
}

// ---------------------------------------------------------------------------
// Launch: QKV GEMM -> causal attention -> proj GEMM
// ---------------------------------------------------------------------------
extern "C" void kernel_launch(void* const* d_in, const int* in_sizes, int n_in,
                              void* d_out, int out_size)
{
    const float* x      = (const float*)d_in[0];
    const float* qkv_w  = (const float*)d_in[1];
    const float* qkv_b  = (const float*)d_in[2];
    const float* proj_w = (const float*)d_in[3];
    const float* proj_b = (const float*)d_in[4];
    float* out = (float*)d_out;

    float *qkv_s, *att_s;
    cudaGetSymbolAddress((void**)&qkv_s, g_qkv);
    cudaGetSymbolAddress((void**)&att_s, g_att);

    const int ATTN_SMEM = (64 * 68 * 2 + 64 * 64) * sizeof(uint32_t);  // 51200 B
    cudaFuncSetAttribute(attn_tc_kernel,
                         cudaFuncAttributeMaxDynamicSharedMemorySize, ATTN_SMEM);

    // 1) QKV GEMM: [8192,1024] @ [1024,3072] + bias
    dim3 g1(QKV_N / 128, MROWS / 128);
    gemm_tf32_kernel<<<g1, 256>>>(x, qkv_w, qkv_b, qkv_s, MROWS, QKV_N, DD);

    // 2) Causal multi-head attention (tensor cores)
    dim3 ga(TT / 64, HH, BB);
    attn_tc_kernel<<<ga, 128, ATTN_SMEM>>>(qkv_s, att_s);

    // 3) Output projection: [8192,1024] @ [1024,1024] + bias
    dim3 g2(DD / 128, MROWS / 128);
    gemm_tf32_kernel<<<g2, 256>>>(att_s, proj_w, proj_b, out, MROWS, DD, DD);
}